// round 13
// baseline (speedup 1.0000x reference)
#include <cuda_runtime.h>
#include <cuda_bf16.h>
#include <cuda_fp16.h>
#include <cstdint>

#define IN_F   256
#define OUT_F  64

#define MAX_NODES 100000
#define MAX_EDGES 1600000
#define MAXDEG    64                  // Poisson(16): P(deg>=64) ~ 2e-18/node

// ---------------- device scratch (static allocation per harness rules) -----
// Invariant across graph replays: g_counts == 0 (re-zeroed inside gather).
__device__ __half g_h16[(size_t)MAX_NODES * OUT_F];      // h = xW + b, fp16 (12.8 MB)
__device__ int    g_counts[MAX_NODES];
__device__ int    g_rank[MAX_EDGES];                     // edge rank within dst bucket
__device__ int2   g_edges[(size_t)MAX_NODES * MAXDEG];   // padded buckets (51.2 MB)

// ===========================================================================
// GEMM: h = x @ W + b  via mma.sync m16n8k16 bf16 (3-term split: hh+hl+lh)
// Epilogue stores h as fp16.
// ===========================================================================
#define TILE_M   128
#define KCHUNK   64
#define XS_PITCH 68
#define WB_PITCH 72
#define SM_XS    0
#define SM_WH    (TILE_M * XS_PITCH * 4)
#define SM_WL    (SM_WH + OUT_F * WB_PITCH * 2)
#define SM_BIAS  (SM_WL + OUT_F * WB_PITCH * 2)
#define SM_TOTAL (SM_BIAS + OUT_F * 4)

#define MMA16816(c, a, b0, b1) \
    asm volatile("mma.sync.aligned.m16n8k16.row.col.f32.bf16.bf16.f32 " \
        "{%0,%1,%2,%3}, {%4,%5,%6,%7}, {%8,%9}, {%0,%1,%2,%3};" \
        : "+f"((c)[0]), "+f"((c)[1]), "+f"((c)[2]), "+f"((c)[3]) \
        : "r"((a)[0]), "r"((a)[1]), "r"((a)[2]), "r"((a)[3]), "r"(b0), "r"(b1))

__device__ __forceinline__ void split2(float vx, float vy, uint32_t& hi, uint32_t& lo) {
    __nv_bfloat16 h0 = __float2bfloat16(vx);
    __nv_bfloat16 h1 = __float2bfloat16(vy);
    __nv_bfloat16 l0 = __float2bfloat16(vx - __bfloat162float(h0));
    __nv_bfloat16 l1 = __float2bfloat16(vy - __bfloat162float(h1));
    __nv_bfloat162 hp(h0, h1), lp(l0, l1);
    hi = *reinterpret_cast<uint32_t*>(&hp);
    lo = *reinterpret_cast<uint32_t*>(&lp);
}

__global__ __launch_bounds__(256) void gemm_mma_kernel(
    const float* __restrict__ x,
    const float* __restrict__ W,
    const float* __restrict__ b,
    int n_nodes)
{
    extern __shared__ char smem[];
    float*         xs = reinterpret_cast<float*>(smem + SM_XS);
    __nv_bfloat16* Wh = reinterpret_cast<__nv_bfloat16*>(smem + SM_WH);
    __nv_bfloat16* Wl = reinterpret_cast<__nv_bfloat16*>(smem + SM_WL);
    float*         bs = reinterpret_cast<float*>(smem + SM_BIAS);

    const int tid  = threadIdx.x;
    const int wid  = tid >> 5;
    const int lane = tid & 31;
    const int row0 = blockIdx.x * TILE_M;
    const int wm   = wid * 16;
    const int lr   = lane >> 2;
    const int lq   = lane & 3;

    if (tid < OUT_F) bs[tid] = b[tid];

    float acc[8][4];
#pragma unroll
    for (int nt = 0; nt < 8; ++nt)
#pragma unroll
        for (int i = 0; i < 4; ++i) acc[nt][i] = 0.f;

    for (int c = 0; c < 4; ++c) {
        __syncthreads();

        for (int i = tid; i < TILE_M * (KCHUNK / 4); i += 256) {
            const int r = i >> 4, q = i & 15;
            float4 v = make_float4(0.f, 0.f, 0.f, 0.f);
            const int grow = row0 + r;
            if (grow < n_nodes)
                v = *reinterpret_cast<const float4*>(&x[(size_t)grow * IN_F + c * KCHUNK + q * 4]);
            *reinterpret_cast<float4*>(&xs[r * XS_PITCH + q * 4]) = v;
        }
        for (int i = tid; i < KCHUNK * OUT_F; i += 256) {
            const int k = i >> 6, n = i & 63;
            const float v = W[(size_t)(c * KCHUNK + k) * OUT_F + n];
            __nv_bfloat16 hi = __float2bfloat16(v);
            __nv_bfloat16 lo = __float2bfloat16(v - __bfloat162float(hi));
            Wh[n * WB_PITCH + k] = hi;
            Wl[n * WB_PITCH + k] = lo;
        }
        __syncthreads();

#pragma unroll
        for (int ks = 0; ks < 4; ++ks) {
            const int kk = ks * 16 + lq * 2;
            const int r  = wm + lr;
            float2 x0 = *reinterpret_cast<const float2*>(&xs[r * XS_PITCH + kk]);
            float2 x1 = *reinterpret_cast<const float2*>(&xs[(r + 8) * XS_PITCH + kk]);
            float2 x2 = *reinterpret_cast<const float2*>(&xs[r * XS_PITCH + kk + 8]);
            float2 x3 = *reinterpret_cast<const float2*>(&xs[(r + 8) * XS_PITCH + kk + 8]);

            uint32_t ah[4], al[4];
            split2(x0.x, x0.y, ah[0], al[0]);
            split2(x1.x, x1.y, ah[1], al[1]);
            split2(x2.x, x2.y, ah[2], al[2]);
            split2(x3.x, x3.y, ah[3], al[3]);

#pragma unroll
            for (int nt = 0; nt < 8; ++nt) {
                const int n = nt * 8 + lr;
                const uint32_t bh0 = *reinterpret_cast<const uint32_t*>(&Wh[n * WB_PITCH + kk]);
                const uint32_t bh1 = *reinterpret_cast<const uint32_t*>(&Wh[n * WB_PITCH + kk + 8]);
                const uint32_t bl0 = *reinterpret_cast<const uint32_t*>(&Wl[n * WB_PITCH + kk]);
                const uint32_t bl1 = *reinterpret_cast<const uint32_t*>(&Wl[n * WB_PITCH + kk + 8]);
                MMA16816(acc[nt], ah, bh0, bh1);
                MMA16816(acc[nt], ah, bl0, bl1);
                MMA16816(acc[nt], al, bh0, bh1);
            }
        }
    }

    const int r_lo = row0 + wm + lr;
    const int r_hi = r_lo + 8;
#pragma unroll
    for (int nt = 0; nt < 8; ++nt) {
        const int col = nt * 8 + lq * 2;
        const float b0 = bs[col], b1 = bs[col + 1];
        if (r_lo < n_nodes) {
            __half2 v = __floats2half2_rn(acc[nt][0] + b0, acc[nt][1] + b1);
            *reinterpret_cast<__half2*>(&g_h16[(size_t)r_lo * OUT_F + col]) = v;
        }
        if (r_hi < n_nodes) {
            __half2 v = __floats2half2_rn(acc[nt][2] + b0, acc[nt][3] + b1);
            *reinterpret_cast<__half2*>(&g_h16[(size_t)r_hi * OUT_F + col]) = v;
        }
    }
}

// ===========================================================================
// Bucket build (NO scan): hist(+rank) -> fixed-stride fill
// ===========================================================================
__global__ void hist_kernel(const int* __restrict__ dst, int n_edges) {
    int e = blockIdx.x * blockDim.x + threadIdx.x;
    if (e < n_edges)
        g_rank[e] = atomicAdd(&g_counts[dst[e]], 1);   // rank within dst bucket
}

__global__ void fill_kernel(const int* __restrict__ src,
                            const int* __restrict__ dst,
                            const float* __restrict__ ew,
                            int n_edges) {
    int e = blockIdx.x * blockDim.x + threadIdx.x;
    if (e >= n_edges) return;
    const size_t p = (size_t)dst[e] * MAXDEG + g_rank[e];
    g_edges[p] = make_int2(src[e], __float_as_int(ew[e]));
}

// ===========================================================================
// Gather (proven R7 config + fixed-stride buckets): 16 lanes/row, unroll-4,
// fp16 h, fp32 accum. Lane 0 re-zeroes counts[row] for the next replay.
// ===========================================================================
__global__ __launch_bounds__(256) void gather_kernel(
    float* __restrict__ out, int n_nodes)
{
    const int idx  = blockIdx.x * blockDim.x + threadIdx.x;
    const int row  = idx >> 4;
    const int lane = idx & 15;
    if (row >= n_nodes) return;

    const int deg = g_counts[row];
    if (lane == 0) g_counts[row] = 0;       // restore invariant for next replay

    const int start = row * MAXDEG;
    const int end   = start + deg;

    float4 acc = make_float4(0.f, 0.f, 0.f, 0.f);
    int j = start;

    for (; j + 4 <= end; j += 4) {
        int2 e0 = g_edges[j];
        int2 e1 = g_edges[j + 1];
        int2 e2 = g_edges[j + 2];
        int2 e3 = g_edges[j + 3];
        __half2 p0a = *reinterpret_cast<const __half2*>(&g_h16[(size_t)e0.x * OUT_F + lane * 4]);
        __half2 p0b = *reinterpret_cast<const __half2*>(&g_h16[(size_t)e0.x * OUT_F + lane * 4 + 2]);
        __half2 p1a = *reinterpret_cast<const __half2*>(&g_h16[(size_t)e1.x * OUT_F + lane * 4]);
        __half2 p1b = *reinterpret_cast<const __half2*>(&g_h16[(size_t)e1.x * OUT_F + lane * 4 + 2]);
        __half2 p2a = *reinterpret_cast<const __half2*>(&g_h16[(size_t)e2.x * OUT_F + lane * 4]);
        __half2 p2b = *reinterpret_cast<const __half2*>(&g_h16[(size_t)e2.x * OUT_F + lane * 4 + 2]);
        __half2 p3a = *reinterpret_cast<const __half2*>(&g_h16[(size_t)e3.x * OUT_F + lane * 4]);
        __half2 p3b = *reinterpret_cast<const __half2*>(&g_h16[(size_t)e3.x * OUT_F + lane * 4 + 2]);
        float w0 = __int_as_float(e0.y), w1 = __int_as_float(e1.y);
        float w2 = __int_as_float(e2.y), w3 = __int_as_float(e3.y);
        float2 f0a = __half22float2(p0a), f0b = __half22float2(p0b);
        float2 f1a = __half22float2(p1a), f1b = __half22float2(p1b);
        float2 f2a = __half22float2(p2a), f2b = __half22float2(p2b);
        float2 f3a = __half22float2(p3a), f3b = __half22float2(p3b);
        acc.x += w0 * f0a.x;  acc.y += w0 * f0a.y;  acc.z += w0 * f0b.x;  acc.w += w0 * f0b.y;
        acc.x += w1 * f1a.x;  acc.y += w1 * f1a.y;  acc.z += w1 * f1b.x;  acc.w += w1 * f1b.y;
        acc.x += w2 * f2a.x;  acc.y += w2 * f2a.y;  acc.z += w2 * f2b.x;  acc.w += w2 * f2b.y;
        acc.x += w3 * f3a.x;  acc.y += w3 * f3a.y;  acc.z += w3 * f3b.x;  acc.w += w3 * f3b.y;
    }
    for (; j < end; ++j) {
        int2 e = g_edges[j];
        __half2 pa = *reinterpret_cast<const __half2*>(&g_h16[(size_t)e.x * OUT_F + lane * 4]);
        __half2 pb = *reinterpret_cast<const __half2*>(&g_h16[(size_t)e.x * OUT_F + lane * 4 + 2]);
        float w = __int_as_float(e.y);
        float2 fa = __half22float2(pa), fb = __half22float2(pb);
        acc.x += w * fa.x;  acc.y += w * fa.y;  acc.z += w * fb.x;  acc.w += w * fb.y;
    }

    *reinterpret_cast<float4*>(&out[(size_t)row * OUT_F + lane * 4]) = acc;
}

// ===========================================================================
// Launch: fork/join stream capture — GEMM branch || bucket branch, then gather.
// ===========================================================================
extern "C" void kernel_launch(void* const* d_in, const int* in_sizes, int n_in,
                              void* d_out, int out_size)
{
    const float* x   = (const float*)d_in[0];
    const int*   es  = (const int*)  d_in[1];
    const int*   ed  = (const int*)  d_in[2];
    const float* ew  = (const float*)d_in[3];
    const float* W   = (const float*)d_in[4];
    const float* b   = (const float*)d_in[5];
    float*       out = (float*)d_out;

    const int n_nodes = in_sizes[0] / IN_F;
    const int n_edges = in_sizes[1];
    const int eblk = (n_edges + 255) / 256;

    cudaFuncSetAttribute(gemm_mma_kernel,
                         cudaFuncAttributeMaxDynamicSharedMemorySize, SM_TOTAL);

    cudaStream_t s2;
    cudaEvent_t evFork, evJoin;
    cudaStreamCreateWithFlags(&s2, cudaStreamNonBlocking);
    cudaEventCreateWithFlags(&evFork, cudaEventDisableTiming);
    cudaEventCreateWithFlags(&evJoin, cudaEventDisableTiming);

    cudaEventRecord(evFork, 0);
    cudaStreamWaitEvent(s2, evFork, 0);

    // Branch A (capture stream): GEMM
    gemm_mma_kernel<<<(n_nodes + TILE_M - 1) / TILE_M, 256, SM_TOTAL>>>(x, W, b, n_nodes);

    // Branch B (s2): bucket build — 2 nodes, no scan
    hist_kernel<<<eblk, 256, 0, s2>>>(ed, n_edges);
    fill_kernel<<<eblk, 256, 0, s2>>>(es, ed, ew, n_edges);

    // join: gather needs both branches
    cudaEventRecord(evJoin, s2);
    cudaStreamWaitEvent(0, evJoin, 0);

    gather_kernel<<<(n_nodes * 16 + 255) / 256, 256>>>(out, n_nodes);

    cudaEventDestroy(evFork);
    cudaEventDestroy(evJoin);
    cudaStreamDestroy(s2);
}

// round 14
// speedup vs baseline: 1.7016x; 1.7016x over previous
#include <cuda_runtime.h>
#include <cuda_bf16.h>
#include <cuda_fp16.h>
#include <cstdint>

#define IN_F   256
#define OUT_F  64

#define MAX_NODES 100000
#define MAX_EDGES 1600000
#define SCAN_BS   256
#define NB        392                 // ceil(100000/256)
#define NT        (NB * SCAN_BS)      // 100352 padded node count

// ---------------- device scratch (static allocation per harness rules) -----
// Invariant across graph replays: g_counts == 0 (re-zeroed inside scanA).
__device__ __half g_h16[(size_t)MAX_NODES * OUT_F]; // h = xW + b, fp16 (12.8 MB)
__device__ int    g_counts[NT];
__device__ int    g_starts[NT];                     // exclusive scan
__device__ int    g_bsum[NB];
__device__ int    g_rank[MAX_EDGES];                // edge rank within its dst bucket
__device__ int2   g_edges[MAX_EDGES];               // packed (src, w_bits), dst-grouped

// ===========================================================================
// GEMM: h = x @ W + b  via mma.sync m16n8k16 bf16 (3-term split: hh+hl+lh)
// Epilogue stores h as fp16.
// ===========================================================================
#define TILE_M   128
#define KCHUNK   64
#define XS_PITCH 68
#define WB_PITCH 72
#define SM_XS    0
#define SM_WH    (TILE_M * XS_PITCH * 4)
#define SM_WL    (SM_WH + OUT_F * WB_PITCH * 2)
#define SM_BIAS  (SM_WL + OUT_F * WB_PITCH * 2)
#define SM_TOTAL (SM_BIAS + OUT_F * 4)

#define MMA16816(c, a, b0, b1) \
    asm volatile("mma.sync.aligned.m16n8k16.row.col.f32.bf16.bf16.f32 " \
        "{%0,%1,%2,%3}, {%4,%5,%6,%7}, {%8,%9}, {%0,%1,%2,%3};" \
        : "+f"((c)[0]), "+f"((c)[1]), "+f"((c)[2]), "+f"((c)[3]) \
        : "r"((a)[0]), "r"((a)[1]), "r"((a)[2]), "r"((a)[3]), "r"(b0), "r"(b1))

__device__ __forceinline__ void split2(float vx, float vy, uint32_t& hi, uint32_t& lo) {
    __nv_bfloat16 h0 = __float2bfloat16(vx);
    __nv_bfloat16 h1 = __float2bfloat16(vy);
    __nv_bfloat16 l0 = __float2bfloat16(vx - __bfloat162float(h0));
    __nv_bfloat16 l1 = __float2bfloat16(vy - __bfloat162float(h1));
    __nv_bfloat162 hp(h0, h1), lp(l0, l1);
    hi = *reinterpret_cast<uint32_t*>(&hp);
    lo = *reinterpret_cast<uint32_t*>(&lp);
}

__global__ __launch_bounds__(256) void gemm_mma_kernel(
    const float* __restrict__ x,
    const float* __restrict__ W,
    const float* __restrict__ b,
    int n_nodes)
{
    extern __shared__ char smem[];
    float*         xs = reinterpret_cast<float*>(smem + SM_XS);
    __nv_bfloat16* Wh = reinterpret_cast<__nv_bfloat16*>(smem + SM_WH);
    __nv_bfloat16* Wl = reinterpret_cast<__nv_bfloat16*>(smem + SM_WL);
    float*         bs = reinterpret_cast<float*>(smem + SM_BIAS);

    const int tid  = threadIdx.x;
    const int wid  = tid >> 5;
    const int lane = tid & 31;
    const int row0 = blockIdx.x * TILE_M;
    const int wm   = wid * 16;
    const int lr   = lane >> 2;
    const int lq   = lane & 3;

    if (tid < OUT_F) bs[tid] = b[tid];

    float acc[8][4];
#pragma unroll
    for (int nt = 0; nt < 8; ++nt)
#pragma unroll
        for (int i = 0; i < 4; ++i) acc[nt][i] = 0.f;

    for (int c = 0; c < 4; ++c) {
        __syncthreads();

        for (int i = tid; i < TILE_M * (KCHUNK / 4); i += 256) {
            const int r = i >> 4, q = i & 15;
            float4 v = make_float4(0.f, 0.f, 0.f, 0.f);
            const int grow = row0 + r;
            if (grow < n_nodes)
                v = *reinterpret_cast<const float4*>(&x[(size_t)grow * IN_F + c * KCHUNK + q * 4]);
            *reinterpret_cast<float4*>(&xs[r * XS_PITCH + q * 4]) = v;
        }
        for (int i = tid; i < KCHUNK * OUT_F; i += 256) {
            const int k = i >> 6, n = i & 63;
            const float v = W[(size_t)(c * KCHUNK + k) * OUT_F + n];
            __nv_bfloat16 hi = __float2bfloat16(v);
            __nv_bfloat16 lo = __float2bfloat16(v - __bfloat162float(hi));
            Wh[n * WB_PITCH + k] = hi;
            Wl[n * WB_PITCH + k] = lo;
        }
        __syncthreads();

#pragma unroll
        for (int ks = 0; ks < 4; ++ks) {
            const int kk = ks * 16 + lq * 2;
            const int r  = wm + lr;
            float2 x0 = *reinterpret_cast<const float2*>(&xs[r * XS_PITCH + kk]);
            float2 x1 = *reinterpret_cast<const float2*>(&xs[(r + 8) * XS_PITCH + kk]);
            float2 x2 = *reinterpret_cast<const float2*>(&xs[r * XS_PITCH + kk + 8]);
            float2 x3 = *reinterpret_cast<const float2*>(&xs[(r + 8) * XS_PITCH + kk + 8]);

            uint32_t ah[4], al[4];
            split2(x0.x, x0.y, ah[0], al[0]);
            split2(x1.x, x1.y, ah[1], al[1]);
            split2(x2.x, x2.y, ah[2], al[2]);
            split2(x3.x, x3.y, ah[3], al[3]);

#pragma unroll
            for (int nt = 0; nt < 8; ++nt) {
                const int n = nt * 8 + lr;
                const uint32_t bh0 = *reinterpret_cast<const uint32_t*>(&Wh[n * WB_PITCH + kk]);
                const uint32_t bh1 = *reinterpret_cast<const uint32_t*>(&Wh[n * WB_PITCH + kk + 8]);
                const uint32_t bl0 = *reinterpret_cast<const uint32_t*>(&Wl[n * WB_PITCH + kk]);
                const uint32_t bl1 = *reinterpret_cast<const uint32_t*>(&Wl[n * WB_PITCH + kk + 8]);
                MMA16816(acc[nt], ah, bh0, bh1);
                MMA16816(acc[nt], ah, bl0, bl1);
                MMA16816(acc[nt], al, bh0, bh1);
            }
        }
    }

    const int r_lo = row0 + wm + lr;
    const int r_hi = r_lo + 8;
#pragma unroll
    for (int nt = 0; nt < 8; ++nt) {
        const int col = nt * 8 + lq * 2;
        const float b0 = bs[col], b1 = bs[col + 1];
        if (r_lo < n_nodes) {
            __half2 v = __floats2half2_rn(acc[nt][0] + b0, acc[nt][1] + b1);
            *reinterpret_cast<__half2*>(&g_h16[(size_t)r_lo * OUT_F + col]) = v;
        }
        if (r_hi < n_nodes) {
            __half2 v = __floats2half2_rn(acc[nt][2] + b0, acc[nt][3] + b1);
            *reinterpret_cast<__half2*>(&g_h16[(size_t)r_hi * OUT_F + col]) = v;
        }
    }
}

// ===========================================================================
// CSR build: hist(+rank) -> scanA -> scanBC (fused) -> rank-addressed fill
// ===========================================================================
__global__ void hist_kernel(const int* __restrict__ dst, int n_edges) {
    int e = blockIdx.x * blockDim.x + threadIdx.x;
    if (e < n_edges)
        g_rank[e] = atomicAdd(&g_counts[dst[e]], 1);   // rank within dst bucket
}

__global__ void scanA_kernel() {
    __shared__ int s[SCAN_BS];
    const int t = threadIdx.x, blk = blockIdx.x, i = blk * SCAN_BS + t;
    const int v = g_counts[i];
    g_counts[i] = 0;                        // restore invariant for next replay
    s[t] = v;
    __syncthreads();
#pragma unroll
    for (int off = 1; off < SCAN_BS; off <<= 1) {
        int u = (t >= off) ? s[t - off] : 0;
        __syncthreads();
        s[t] += u;
        __syncthreads();
    }
    g_starts[i] = s[t] - v;
    if (t == SCAN_BS - 1) g_bsum[blk] = s[t];
}

// Fused scanB+scanC: block blk adds sum(bsum[0..blk-1]) to its 256 starts.
// bsum is 392 ints, L2-hot: masked block reduction per block is cheap.
__global__ __launch_bounds__(SCAN_BS) void scanBC_kernel() {
    __shared__ int s[SCAN_BS];
    const int t = threadIdx.x, blk = blockIdx.x;
    int v = 0;
    if (t < blk)                 v += g_bsum[t];
    if (t + SCAN_BS < blk)       v += g_bsum[t + SCAN_BS];   // NB < 2*SCAN_BS
    s[t] = v;
    __syncthreads();
#pragma unroll
    for (int off = SCAN_BS / 2; off > 0; off >>= 1) {
        if (t < off) s[t] += s[t + off];
        __syncthreads();
    }
    g_starts[blk * SCAN_BS + t] += s[0];
}

__global__ void fill_kernel(const int* __restrict__ src,
                            const int* __restrict__ dst,
                            const float* __restrict__ ew,
                            int n_edges) {
    int e = blockIdx.x * blockDim.x + threadIdx.x;
    if (e >= n_edges) return;
    const int p = g_starts[dst[e]] + g_rank[e];        // no atomic
    g_edges[p] = make_int2(src[e], __float_as_int(ew[e]));
}

// ===========================================================================
// Gather (proven config): 16 lanes/row, unroll-4, fp16 h, fp32 accum.
// ===========================================================================
__global__ __launch_bounds__(256) void gather_kernel(
    float* __restrict__ out, int n_nodes)
{
    const int idx  = blockIdx.x * blockDim.x + threadIdx.x;
    const int row  = idx >> 4;
    const int lane = idx & 15;
    if (row >= n_nodes) return;

    const int start = g_starts[row];
    const int end   = g_starts[row + 1];

    float4 acc = make_float4(0.f, 0.f, 0.f, 0.f);
    int j = start;

    for (; j + 4 <= end; j += 4) {
        int2 e0 = g_edges[j];
        int2 e1 = g_edges[j + 1];
        int2 e2 = g_edges[j + 2];
        int2 e3 = g_edges[j + 3];
        __half2 p0a = *reinterpret_cast<const __half2*>(&g_h16[(size_t)e0.x * OUT_F + lane * 4]);
        __half2 p0b = *reinterpret_cast<const __half2*>(&g_h16[(size_t)e0.x * OUT_F + lane * 4 + 2]);
        __half2 p1a = *reinterpret_cast<const __half2*>(&g_h16[(size_t)e1.x * OUT_F + lane * 4]);
        __half2 p1b = *reinterpret_cast<const __half2*>(&g_h16[(size_t)e1.x * OUT_F + lane * 4 + 2]);
        __half2 p2a = *reinterpret_cast<const __half2*>(&g_h16[(size_t)e2.x * OUT_F + lane * 4]);
        __half2 p2b = *reinterpret_cast<const __half2*>(&g_h16[(size_t)e2.x * OUT_F + lane * 4 + 2]);
        __half2 p3a = *reinterpret_cast<const __half2*>(&g_h16[(size_t)e3.x * OUT_F + lane * 4]);
        __half2 p3b = *reinterpret_cast<const __half2*>(&g_h16[(size_t)e3.x * OUT_F + lane * 4 + 2]);
        float w0 = __int_as_float(e0.y), w1 = __int_as_float(e1.y);
        float w2 = __int_as_float(e2.y), w3 = __int_as_float(e3.y);
        float2 f0a = __half22float2(p0a), f0b = __half22float2(p0b);
        float2 f1a = __half22float2(p1a), f1b = __half22float2(p1b);
        float2 f2a = __half22float2(p2a), f2b = __half22float2(p2b);
        float2 f3a = __half22float2(p3a), f3b = __half22float2(p3b);
        acc.x += w0 * f0a.x;  acc.y += w0 * f0a.y;  acc.z += w0 * f0b.x;  acc.w += w0 * f0b.y;
        acc.x += w1 * f1a.x;  acc.y += w1 * f1a.y;  acc.z += w1 * f1b.x;  acc.w += w1 * f1b.y;
        acc.x += w2 * f2a.x;  acc.y += w2 * f2a.y;  acc.z += w2 * f2b.x;  acc.w += w2 * f2b.y;
        acc.x += w3 * f3a.x;  acc.y += w3 * f3a.y;  acc.z += w3 * f3b.x;  acc.w += w3 * f3b.y;
    }
    for (; j < end; ++j) {
        int2 e = g_edges[j];
        __half2 pa = *reinterpret_cast<const __half2*>(&g_h16[(size_t)e.x * OUT_F + lane * 4]);
        __half2 pb = *reinterpret_cast<const __half2*>(&g_h16[(size_t)e.x * OUT_F + lane * 4 + 2]);
        float w = __int_as_float(e.y);
        float2 fa = __half22float2(pa), fb = __half22float2(pb);
        acc.x += w * fa.x;  acc.y += w * fa.y;  acc.z += w * fb.x;  acc.w += w * fb.y;
    }

    *reinterpret_cast<float4*>(&out[(size_t)row * OUT_F + lane * 4]) = acc;
}

// ===========================================================================
// Launch: fork/join stream capture — GEMM branch || CSR branch, then gather.
// ===========================================================================
extern "C" void kernel_launch(void* const* d_in, const int* in_sizes, int n_in,
                              void* d_out, int out_size)
{
    const float* x   = (const float*)d_in[0];
    const int*   es  = (const int*)  d_in[1];
    const int*   ed  = (const int*)  d_in[2];
    const float* ew  = (const float*)d_in[3];
    const float* W   = (const float*)d_in[4];
    const float* b   = (const float*)d_in[5];
    float*       out = (float*)d_out;

    const int n_nodes = in_sizes[0] / IN_F;
    const int n_edges = in_sizes[1];
    const int eblk = (n_edges + 255) / 256;

    cudaFuncSetAttribute(gemm_mma_kernel,
                         cudaFuncAttributeMaxDynamicSharedMemorySize, SM_TOTAL);

    cudaStream_t s2;
    cudaEvent_t evFork, evJoin;
    cudaStreamCreateWithFlags(&s2, cudaStreamNonBlocking);
    cudaEventCreateWithFlags(&evFork, cudaEventDisableTiming);
    cudaEventCreateWithFlags(&evJoin, cudaEventDisableTiming);

    cudaEventRecord(evFork, 0);
    cudaStreamWaitEvent(s2, evFork, 0);

    // Branch A (capture stream): GEMM
    gemm_mma_kernel<<<(n_nodes + TILE_M - 1) / TILE_M, 256, SM_TOTAL>>>(x, W, b, n_nodes);

    // Branch B (s2): CSR build — 4 nodes (counts zeroed by scanA of prev run)
    hist_kernel<<<eblk, 256, 0, s2>>>(ed, n_edges);
    scanA_kernel<<<NB, SCAN_BS, 0, s2>>>();
    scanBC_kernel<<<NB, SCAN_BS, 0, s2>>>();
    fill_kernel<<<eblk, 256, 0, s2>>>(es, ed, ew, n_edges);

    // join: gather needs both branches
    cudaEventRecord(evJoin, s2);
    cudaStreamWaitEvent(0, evJoin, 0);

    gather_kernel<<<(n_nodes * 16 + 255) / 256, 256>>>(out, n_nodes);

    cudaEventDestroy(evFork);
    cudaEventDestroy(evJoin);
    cudaStreamDestroy(s2);
}